// round 17
// baseline (speedup 1.0000x reference)
#include <cuda_runtime.h>
#include <cuda_bf16.h>
#include <cstdint>

#define NN 8192
#define FD 256
#define HD 64
#define HE 80      // h_ext columns (64 h + ones col 64 + 15 zero)
#define NTC 72     // C columns (deg at col 64)
#define BM 128
#define BK 64
#define KSPLIT 4
#define NITL (NN / BK / KSPLIT)   // 32 k-tiles per CTA
#define SB_STR 88                 // bf16 per sB row (conflict-free trans ldmatrix)
#define SB_TILE (BK * SB_STR)     // 5632 bf16 = 11264 B
#define SA_BYTES (BM * 128)       // 16384 B per A stage (bf16, 128B rows)
#define SMEM_MM (2 * SA_BYTES + 3 * SB_TILE * 2)      // 66560
#define SMEM_HMM (2 * SA_BYTES + FD * SB_STR * 2)     // 77824

#define BM2 64
#define SB2_STR 264               // bf16 per Wp^T k-row (33*16B -> cf ldmatrix)
#define SY_STR 264                // floats per sY row
#define SMEM_TF (BM2 * SY_STR * 4)   // 67584 (> 8192 + 64*SB2_STR*2)

// device scratch (static allocation only — no cudaMalloc allowed)
__device__ __align__(16) __nv_bfloat16 g_hext[NN * HE];
__device__ __align__(16) __nv_bfloat16 g_wt[FD * HD];   // Wt^T bf16 [k][c]
__device__ __align__(16) __nv_bfloat16 g_wp[HD * FD];   // Wp^T bf16 [k][n]
__device__ __align__(16) float g_Cp[KSPLIT * NN * NTC];

typedef unsigned int uint;

__device__ __forceinline__ void cpa16(void* dst, const void* src) {
    uint32_t d = (uint32_t)__cvta_generic_to_shared(dst);
    asm volatile("cp.async.cg.shared.global [%0], [%1], 16;\n" :: "r"(d), "l"(src));
}

// ---------------------------------------------------------------------------
// K_w: g_wt[k][c] = bf16(Wt[c][k]);  K_wp: g_wp[k][n] = bf16(Wp[n][k])
// ---------------------------------------------------------------------------
__global__ void __launch_bounds__(256) k_w(const float* __restrict__ Wt) {
    int i = blockIdx.x * 256 + threadIdx.x;   // grid 64 -> 16384 elems
    int c = i >> 8, k = i & 255;
    g_wt[(size_t)k * HD + c] = __float2bfloat16(Wt[(size_t)c * FD + k]);
}
__global__ void __launch_bounds__(256) k_wp(const float* __restrict__ Wp) {
    int i = blockIdx.x * 256 + threadIdx.x;   // grid 64 -> 16384 elems
    int n = i >> 6, k = i & 63;               // read Wp[n][k] coalesced
    g_wp[(size_t)k * FD + n] = __float2bfloat16(Wp[(size_t)n * HD + k]);
}

// ---------------------------------------------------------------------------
// K_hmm: h = x @ Wt^T + bt -> g_hext bf16 (80 cols; col 64 = 1, 65-79 = 0)
// ---------------------------------------------------------------------------
__global__ void __launch_bounds__(256) k_hmm(const float* __restrict__ x,
                                             const float* __restrict__ bt) {
    extern __shared__ __align__(16) char dynh[];
    char* sA = dynh;                                         // 2 x 16384 B
    __nv_bfloat16* sBW = (__nv_bfloat16*)(dynh + 2 * SA_BYTES);  // [256][88]

    const int tid = threadIdx.x;
    const int warp = tid >> 5, lane = tid & 31;
    const int rowBase = blockIdx.x * BM;    // grid 64
    const int mgroup = warp & 3;
    const int nset = warp >> 2;             // 0: cols 0-31, 1: cols 32-63

    const int arow = tid >> 4;
    const int c16 = tid & 15;
    const float* apx = x + (size_t)(rowBase + arow) * FD + c16 * 4;

#pragma unroll
    for (int j = 0; j < 8; j++) {
        int i = tid + j * 256;
        int r = i >> 3, cc = i & 7;
        cpa16((char*)sBW + (r * SB_STR + cc * 8) * 2, g_wt + (size_t)r * HD + cc * 8);
    }
    asm volatile("cp.async.commit_group;\n");

    float acc[2][4][4];
#pragma unroll
    for (int a = 0; a < 2; a++)
#pragma unroll
        for (int i = 0; i < 4; i++)
            acc[a][i][0] = acc[a][i][1] = acc[a][i][2] = acc[a][i][3] = 0.f;

    float4 rX[8];
#pragma unroll
    for (int j = 0; j < 8; j++) rX[j] = *(const float4*)(apx + (size_t)(16 * j) * FD);

    const uint32_t sAu = (uint32_t)__cvta_generic_to_shared(sA);
    const int sts_row_off = (((c16 >> 1) ^ (arow & 7)) * 16) + (c16 & 1) * 8;

#pragma unroll
    for (int kt = 0; kt < 4; ++kt) {
        {
            const uint32_t abase = sAu + (kt & 1) * SA_BYTES;
#pragma unroll
            for (int j = 0; j < 8; j++) {
                __nv_bfloat162 h0 = __floats2bfloat162_rn(rX[j].x, rX[j].y);
                __nv_bfloat162 h1 = __floats2bfloat162_rn(rX[j].z, rX[j].w);
                uint lo = *reinterpret_cast<uint*>(&h0);
                uint hi = *reinterpret_cast<uint*>(&h1);
                uint32_t d = abase + (arow + 16 * j) * 128 + sts_row_off;
                asm volatile("st.shared.v2.b32 [%0], {%1, %2};"
                             :: "r"(d), "r"(lo), "r"(hi) : "memory");
            }
        }
        if (kt < 3) {
#pragma unroll
            for (int j = 0; j < 8; j++)
                rX[j] = *(const float4*)(apx + (kt + 1) * 64 + (size_t)(16 * j) * FD);
        }
        if (kt == 0) asm volatile("cp.async.wait_group 0;\n");
        __syncthreads();

        const uint32_t sAb = sAu + (kt & 1) * SA_BYTES;
#pragma unroll
        for (int ks = 0; ks < 4; ++ks) {
            uint a[2][4];
#pragma unroll
            for (int mf = 0; mf < 2; mf++) {
                int row = mgroup * 32 + mf * 16 + (lane & 15);
                int chunk = 2 * ks + (lane >> 4);
                uint32_t addr = sAb + row * 128 + ((chunk ^ (lane & 7)) * 16);
                asm volatile("ldmatrix.sync.aligned.m8n8.x4.shared.b16 {%0,%1,%2,%3},[%4];\n"
                             : "=r"(a[mf][0]), "=r"(a[mf][1]), "=r"(a[mf][2]), "=r"(a[mf][3])
                             : "r"(addr));
            }
            const int kk = kt * 64 + ks * 16 + (lane & 15);
            uint b[8];
#pragma unroll
            for (int pl = 0; pl < 2; pl++) {
                uint32_t addr = (uint32_t)__cvta_generic_to_shared(
                    &sBW[kk * SB_STR + nset * 32 + pl * 16 + ((lane >> 4) << 3)]);
                asm volatile("ldmatrix.sync.aligned.m8n8.x4.trans.shared.b16 {%0,%1,%2,%3},[%4];\n"
                             : "=r"(b[4 * pl]), "=r"(b[4 * pl + 1]),
                               "=r"(b[4 * pl + 2]), "=r"(b[4 * pl + 3])
                             : "r"(addr));
            }
#pragma unroll
            for (int mf = 0; mf < 2; mf++) {
#pragma unroll
                for (int t = 0; t < 4; t++) {
                    asm volatile("mma.sync.aligned.m16n8k16.row.col.f32.bf16.bf16.f32 "
                                 "{%0,%1,%2,%3},{%4,%5,%6,%7},{%8,%9},{%0,%1,%2,%3};\n"
                                 : "+f"(acc[mf][t][0]), "+f"(acc[mf][t][1]),
                                   "+f"(acc[mf][t][2]), "+f"(acc[mf][t][3])
                                 : "r"(a[mf][0]), "r"(a[mf][1]), "r"(a[mf][2]), "r"(a[mf][3]),
                                   "r"(b[2 * t]), "r"(b[2 * t + 1]));
                }
            }
        }
        __syncthreads();
    }

    const int gr = lane >> 2, gc = (lane & 3) * 2;
#pragma unroll
    for (int t = 0; t < 4; t++) {
        const int c0 = nset * 32 + t * 8 + gc;
        const float b0 = bt[c0], b1 = bt[c0 + 1];
#pragma unroll
        for (int mf = 0; mf < 2; mf++) {
            int row = rowBase + mgroup * 32 + mf * 16 + gr;
            __nv_bfloat162 v0 = __floats2bfloat162_rn(acc[mf][t][0] + b0, acc[mf][t][1] + b1);
            __nv_bfloat162 v1 = __floats2bfloat162_rn(acc[mf][t][2] + b0, acc[mf][t][3] + b1);
            *reinterpret_cast<__nv_bfloat162*>(&g_hext[(size_t)row * HE + c0]) = v0;
            *reinterpret_cast<__nv_bfloat162*>(&g_hext[(size_t)(row + 8) * HE + c0]) = v1;
        }
    }
    {
        int row = rowBase + (tid >> 1), half = tid & 1;
        uint4 v = (half == 0) ? make_uint4(0x00003F80u, 0u, 0u, 0u)
                              : make_uint4(0u, 0u, 0u, 0u);
        *reinterpret_cast<uint4*>(&g_hext[(size_t)row * HE + 64 + half * 8]) = v;
    }
}

// ---------------------------------------------------------------------------
// K_mm: Cp[kq] = adj(0/1 -> bf16) @ h_ext (N=72 incl deg col) — R10-proven.
// ---------------------------------------------------------------------------
__device__ __forceinline__ void loadB(__nv_bfloat16* sB, int ktg, int tid) {
#pragma unroll
    for (int j = 0; j < 3; j++) {
        int i = tid + j * 256;
        if (i < 640) {
            int r = i / 10, cc = i % 10;
            cpa16(sB + r * SB_STR + cc * 8, g_hext + (size_t)(ktg * BK + r) * HE + cc * 8);
        }
    }
    asm volatile("cp.async.commit_group;\n");
}

__global__ void __launch_bounds__(256, 2) k_adj_mm(const int* __restrict__ adj) {
    extern __shared__ __align__(16) char dyn[];
    char* sA = dyn;
    __nv_bfloat16* sB0 = (__nv_bfloat16*)(dyn + 2 * SA_BYTES);

    const int tid = threadIdx.x;
    const int warp = tid >> 5, lane = tid & 31;
    const int mtile = blockIdx.x >> 2, kq = blockIdx.x & 3;
    const int rowBase = mtile * BM;
    const int kbase = kq * (NN / KSPLIT);
    const int mgroup = warp & 3;
    const int nset = warp >> 2;

    const int arow = tid >> 4;
    const int c16 = tid & 15;
    const int* ap = adj + (size_t)(rowBase + arow) * NN + kbase + c16 * 4;

    float acc[2][5][4];
#pragma unroll
    for (int a = 0; a < 2; a++)
#pragma unroll
        for (int i = 0; i < 5; i++)
            acc[a][i][0] = acc[a][i][1] = acc[a][i][2] = acc[a][i][3] = 0.f;

    int4 rA[8];
#pragma unroll
    for (int j = 0; j < 8; j++) rA[j] = *(const int4*)(ap + (size_t)(16 * j) * NN);

    loadB(sB0 + 0 * SB_TILE, kq * NITL + 0, tid);
    loadB(sB0 + 1 * SB_TILE, kq * NITL + 1, tid);

    const uint32_t sAu = (uint32_t)__cvta_generic_to_shared(sA);
    const int sts_row_off = (((c16 >> 1) ^ (arow & 7)) * 16) + (c16 & 1) * 8;

    for (int kt = 0; kt < NITL; ++kt) {
        {
            const uint32_t abase = sAu + (kt & 1) * SA_BYTES;
#pragma unroll
            for (int j = 0; j < 8; j++) {
                int4 v = rA[j];
                uint lo = (uint)v.x * 0x3F80u + (uint)v.y * 0x3F800000u;
                uint hi = (uint)v.z * 0x3F80u + (uint)v.w * 0x3F800000u;
                uint32_t d = abase + (arow + 16 * j) * 128 + sts_row_off;
                asm volatile("st.shared.v2.b32 [%0], {%1, %2};"
                             :: "r"(d), "r"(lo), "r"(hi) : "memory");
            }
        }
        if (kt + 1 < NITL) {
            const int* np = ap + (size_t)(kt + 1) * BK;
#pragma unroll
            for (int j = 0; j < 8; j++) rA[j] = *(const int4*)(np + (size_t)(16 * j) * NN);
        }

        asm volatile("cp.async.wait_group 1;\n");
        __syncthreads();
        if (kt + 2 < NITL) loadB(sB0 + ((kt + 2) % 3) * SB_TILE, kq * NITL + kt + 2, tid);

        const __nv_bfloat16* sB = sB0 + (kt % 3) * SB_TILE;
        const uint32_t sAb = sAu + (kt & 1) * SA_BYTES;

#pragma unroll
        for (int ks = 0; ks < 4; ++ks) {
            uint a[2][4];
#pragma unroll
            for (int mf = 0; mf < 2; mf++) {
                int row = mgroup * 32 + mf * 16 + (lane & 15);
                int chunk = 2 * ks + (lane >> 4);
                uint32_t addr = sAb + row * 128 + ((chunk ^ (lane & 7)) * 16);
                asm volatile("ldmatrix.sync.aligned.m8n8.x4.shared.b16 {%0,%1,%2,%3},[%4];\n"
                             : "=r"(a[mf][0]), "=r"(a[mf][1]), "=r"(a[mf][2]), "=r"(a[mf][3])
                             : "r"(addr));
            }
            const int kk = ks * 16 + (lane & 15);
            if (nset == 0) {
                uint b[10];
#pragma unroll
                for (int pl = 0; pl < 2; pl++) {
                    uint32_t addr = (uint32_t)__cvta_generic_to_shared(
                        &sB[kk * SB_STR + pl * 16 + ((lane >> 4) << 3)]);
                    asm volatile("ldmatrix.sync.aligned.m8n8.x4.trans.shared.b16 {%0,%1,%2,%3},[%4];\n"
                                 : "=r"(b[4 * pl]), "=r"(b[4 * pl + 1]),
                                   "=r"(b[4 * pl + 2]), "=r"(b[4 * pl + 3])
                                 : "r"(addr));
                }
                {
                    uint32_t addr = (uint32_t)__cvta_generic_to_shared(&sB[kk * SB_STR + 32]);
                    asm volatile("ldmatrix.sync.aligned.m8n8.x2.trans.shared.b16 {%0,%1},[%2];\n"
                                 : "=r"(b[8]), "=r"(b[9]) : "r"(addr));
                }
#pragma unroll
                for (int mf = 0; mf < 2; mf++) {
#pragma unroll
                    for (int t = 0; t < 5; t++) {
                        asm volatile("mma.sync.aligned.m16n8k16.row.col.f32.bf16.bf16.f32 "
                                     "{%0,%1,%2,%3},{%4,%5,%6,%7},{%8,%9},{%0,%1,%2,%3};\n"
                                     : "+f"(acc[mf][t][0]), "+f"(acc[mf][t][1]),
                                       "+f"(acc[mf][t][2]), "+f"(acc[mf][t][3])
                                     : "r"(a[mf][0]), "r"(a[mf][1]), "r"(a[mf][2]), "r"(a[mf][3]),
                                       "r"(b[2 * t]), "r"(b[2 * t + 1]));
                    }
                }
            } else {
                uint b[8];
#pragma unroll
                for (int pl = 0; pl < 2; pl++) {
                    uint32_t addr = (uint32_t)__cvta_generic_to_shared(
                        &sB[kk * SB_STR + 40 + pl * 16 + ((lane >> 4) << 3)]);
                    asm volatile("ldmatrix.sync.aligned.m8n8.x4.trans.shared.b16 {%0,%1,%2,%3},[%4];\n"
                                 : "=r"(b[4 * pl]), "=r"(b[4 * pl + 1]),
                                   "=r"(b[4 * pl + 2]), "=r"(b[4 * pl + 3])
                                 : "r"(addr));
                }
#pragma unroll
                for (int mf = 0; mf < 2; mf++) {
#pragma unroll
                    for (int t = 0; t < 4; t++) {
                        asm volatile("mma.sync.aligned.m16n8k16.row.col.f32.bf16.bf16.f32 "
                                     "{%0,%1,%2,%3},{%4,%5,%6,%7},{%8,%9},{%0,%1,%2,%3};\n"
                                     : "+f"(acc[mf][t][0]), "+f"(acc[mf][t][1]),
                                       "+f"(acc[mf][t][2]), "+f"(acc[mf][t][3])
                                     : "r"(a[mf][0]), "r"(a[mf][1]), "r"(a[mf][2]), "r"(a[mf][3]),
                                       "r"(b[2 * t]), "r"(b[2 * t + 1]));
                    }
                }
            }
        }
    }

    float* Cout = g_Cp + (size_t)kq * NN * NTC;
    const int gr = lane >> 2, gc = (lane & 3) * 2;
    const int ntiles = (nset == 0) ? 5 : 4;
#pragma unroll
    for (int mf = 0; mf < 2; mf++) {
#pragma unroll
        for (int lt = 0; lt < 5; ++lt) {
            if (lt >= ntiles) break;
            const int gt = (nset == 0) ? lt : (5 + lt);
            size_t base = (size_t)(rowBase + mgroup * 32 + mf * 16 + gr) * NTC + gt * 8 + gc;
            Cout[base] = acc[mf][lt][0];
            Cout[base + 1] = acc[mf][lt][1];
            Cout[base + (size_t)8 * NTC] = acc[mf][lt][2];
            Cout[base + (size_t)8 * NTC + 1] = acc[mf][lt][3];
        }
    }
}

// ---------------------------------------------------------------------------
// K_tf_ln: nb = (sum Cp)/deg (bf16) -> tensor GEMM tf = nb @ Wp^T ->
//          y = x + tf + bp -> LayerNorm -> out.   BM2=64 rows/CTA, grid 128.
// ---------------------------------------------------------------------------
__global__ void __launch_bounds__(256) k_tf_ln(const float* __restrict__ x,
                                               const float* __restrict__ bp,
                                               const float* __restrict__ gamma,
                                               const float* __restrict__ beta,
                                               float* __restrict__ out) {
    extern __shared__ __align__(16) char dynt[];
    char* sA = dynt;                                       // 8192 B bf16 [64][64] swz
    __nv_bfloat16* sB = (__nv_bfloat16*)(dynt + 8192);     // [64][264]
    float* sY = (float*)dynt;                              // [64][264] (after GEMM)
    __shared__ float sdeg[BM2];

    const int tid = threadIdx.x;
    const int warp = tid >> 5, lane = tid & 31;
    const int rowBase = blockIdx.x * BM2;    // grid 128
    const int mgroup = warp & 3;             // 16-row group
    const int nset = warp >> 2;              // 0: cols 0-127, 1: cols 128-255

    // deg per row
    if (tid < BM2) {
        size_t rb = (size_t)(rowBase + tid) * NTC + HD;
        float d = 0.f;
#pragma unroll
        for (int q = 0; q < KSPLIT; q++) d += g_Cp[(size_t)q * NN * NTC + rb];
        sdeg[tid] = d;
    }

    // B: Wp^T 64x256 bf16 -> smem (2048 16B chunks)
#pragma unroll
    for (int j = 0; j < 8; j++) {
        int i = tid + j * 256;
        int r = i >> 5, cc = i & 31;
        cpa16((char*)sB + (r * SB2_STR + cc * 8) * 2, g_wp + (size_t)r * FD + cc * 8);
    }
    asm volatile("cp.async.commit_group;\n");
    __syncthreads();    // sdeg ready

    // nb -> bf16 swizzled A tile (4 cols x 4 row-blocks per thread)
    const uint32_t sAu = (uint32_t)__cvta_generic_to_shared(sA);
    {
        const int cc4 = (tid & 15) * 4;
        const int chunk = (tid & 15) >> 1;
        const int off = (tid & 1) * 8;
#pragma unroll
        for (int j = 0; j < 4; j++) {
            int r = (tid >> 4) + 16 * j;
            size_t rb = (size_t)(rowBase + r) * NTC + cc4;
            float vx = 0.f, vy = 0.f, vz = 0.f, vw = 0.f;
#pragma unroll
            for (int q = 0; q < KSPLIT; q++) {
                float4 p = *(const float4*)(g_Cp + (size_t)q * NN * NTC + rb);
                vx += p.x; vy += p.y; vz += p.z; vw += p.w;
            }
            float d = sdeg[r];
            float inv = (d > 0.5f) ? 1.f / d : 0.f;
            __nv_bfloat162 b0 = __floats2bfloat162_rn(vx * inv, vy * inv);
            __nv_bfloat162 b1 = __floats2bfloat162_rn(vz * inv, vw * inv);
            uint lo = *reinterpret_cast<uint*>(&b0);
            uint hi = *reinterpret_cast<uint*>(&b1);
            uint32_t a = sAu + r * 128 + ((chunk ^ (r & 7)) * 16) + off;
            asm volatile("st.shared.v2.b32 [%0], {%1, %2};"
                         :: "r"(a), "r"(lo), "r"(hi) : "memory");
        }
    }
    asm volatile("cp.async.wait_group 0;\n");
    __syncthreads();

    // GEMM: 4 k-steps x 16 n-tiles per warp
    float acc[16][4];
#pragma unroll
    for (int i = 0; i < 16; i++)
        acc[i][0] = acc[i][1] = acc[i][2] = acc[i][3] = 0.f;

#pragma unroll
    for (int ks = 0; ks < 4; ++ks) {
        uint a[4];
        {
            int row = mgroup * 16 + (lane & 15);
            int chunk = 2 * ks + (lane >> 4);
            uint32_t addr = sAu + row * 128 + ((chunk ^ (lane & 7)) * 16);
            asm volatile("ldmatrix.sync.aligned.m8n8.x4.shared.b16 {%0,%1,%2,%3},[%4];\n"
                         : "=r"(a[0]), "=r"(a[1]), "=r"(a[2]), "=r"(a[3]) : "r"(addr));
        }
        const int kk = ks * 16 + (lane & 15);
#pragma unroll
        for (int pl = 0; pl < 8; ++pl) {
            uint b0, b1, b2, b3;
            uint32_t addr = (uint32_t)__cvta_generic_to_shared(
                &sB[kk * SB2_STR + nset * 128 + pl * 16 + ((lane >> 4) << 3)]);
            asm volatile("ldmatrix.sync.aligned.m8n8.x4.trans.shared.b16 {%0,%1,%2,%3},[%4];\n"
                         : "=r"(b0), "=r"(b1), "=r"(b2), "=r"(b3) : "r"(addr));
            asm volatile("mma.sync.aligned.m16n8k16.row.col.f32.bf16.bf16.f32 "
                         "{%0,%1,%2,%3},{%4,%5,%6,%7},{%8,%9},{%0,%1,%2,%3};\n"
                         : "+f"(acc[2 * pl][0]), "+f"(acc[2 * pl][1]),
                           "+f"(acc[2 * pl][2]), "+f"(acc[2 * pl][3])
                         : "r"(a[0]), "r"(a[1]), "r"(a[2]), "r"(a[3]), "r"(b0), "r"(b1));
            asm volatile("mma.sync.aligned.m16n8k16.row.col.f32.bf16.bf16.f32 "
                         "{%0,%1,%2,%3},{%4,%5,%6,%7},{%8,%9},{%0,%1,%2,%3};\n"
                         : "+f"(acc[2 * pl + 1][0]), "+f"(acc[2 * pl + 1][1]),
                           "+f"(acc[2 * pl + 1][2]), "+f"(acc[2 * pl + 1][3])
                         : "r"(a[0]), "r"(a[1]), "r"(a[2]), "r"(a[3]), "r"(b2), "r"(b3));
        }
    }
    __syncthreads();   // done reading sA/sB; sY may overwrite

    // fragments -> sY
    {
        const int gr = lane >> 2, gc = (lane & 3) * 2;
        const int r0l = mgroup * 16 + gr;
#pragma unroll
        for (int nt = 0; nt < 16; ++nt) {
            int col = nset * 128 + nt * 8 + gc;
            *(float2*)(sY + r0l * SY_STR + col) = make_float2(acc[nt][0], acc[nt][1]);
            *(float2*)(sY + (r0l + 8) * SY_STR + col) = make_float2(acc[nt][2], acc[nt][3]);
        }
    }
    __syncthreads();

    // LayerNorm: warp per row, 8 iterations
    const float4 bp0 = ((const float4*)bp)[lane], bp1 = ((const float4*)bp)[32 + lane];
    const float4 g0 = ((const float4*)gamma)[lane], g1 = ((const float4*)gamma)[32 + lane];
    const float4 be0 = ((const float4*)beta)[lane], be1 = ((const float4*)beta)[32 + lane];
#pragma unroll
    for (int it = 0; it < 8; ++it) {
        const int row = it * 8 + warp;
        const float4* xr = (const float4*)(x + (size_t)(rowBase + row) * FD);
        float4 t0 = *(const float4*)(sY + row * SY_STR + lane * 4);
        float4 t1 = *(const float4*)(sY + row * SY_STR + 128 + lane * 4);
        float4 x0 = xr[lane], x1 = xr[32 + lane];
        float4 y0, y1;
        y0.x = x0.x + t0.x + bp0.x; y0.y = x0.y + t0.y + bp0.y;
        y0.z = x0.z + t0.z + bp0.z; y0.w = x0.w + t0.w + bp0.w;
        y1.x = x1.x + t1.x + bp1.x; y1.y = x1.y + t1.y + bp1.y;
        y1.z = x1.z + t1.z + bp1.z; y1.w = x1.w + t1.w + bp1.w;
        float s = y0.x + y0.y + y0.z + y0.w + y1.x + y1.y + y1.z + y1.w;
        float q = y0.x * y0.x + y0.y * y0.y + y0.z * y0.z + y0.w * y0.w +
                  y1.x * y1.x + y1.y * y1.y + y1.z * y1.z + y1.w * y1.w;
#pragma unroll
        for (int o = 16; o > 0; o >>= 1) {
            s += __shfl_xor_sync(0xffffffffu, s, o);
            q += __shfl_xor_sync(0xffffffffu, q, o);
        }
        float mu = s * (1.f / FD);
        float var = q * (1.f / FD) - mu * mu;
        float rs = rsqrtf(var + 1e-5f);
        float4* outr = (float4*)(out + (size_t)(rowBase + row) * FD);
        float4 o0, o1;
        o0.x = g0.x * (y0.x - mu) * rs + be0.x; o0.y = g0.y * (y0.y - mu) * rs + be0.y;
        o0.z = g0.z * (y0.z - mu) * rs + be0.z; o0.w = g0.w * (y0.w - mu) * rs + be0.w;
        o1.x = g1.x * (y1.x - mu) * rs + be1.x; o1.y = g1.y * (y1.y - mu) * rs + be1.y;
        o1.z = g1.z * (y1.z - mu) * rs + be1.z; o1.w = g1.w * (y1.w - mu) * rs + be1.w;
        outr[lane] = o0;
        outr[32 + lane] = o1;
    }
}

// ---------------------------------------------------------------------------
extern "C" void kernel_launch(void* const* d_in, const int* in_sizes, int n_in,
                              void* d_out, int out_size) {
    const float* x     = (const float*)d_in[0];
    const int*   adj   = (const int*)d_in[1];
    const float* Wt    = (const float*)d_in[2];
    const float* bt    = (const float*)d_in[3];
    // d_in[4] (Wa), d_in[5] (ba): mathematically irrelevant — softmax over
    // row-constant scores collapses to 1/deg regardless of s.
    const float* Wp    = (const float*)d_in[6];
    const float* bp    = (const float*)d_in[7];
    const float* gamma = (const float*)d_in[8];
    const float* beta  = (const float*)d_in[9];
    float* out = (float*)d_out;

    cudaFuncSetAttribute(k_adj_mm, cudaFuncAttributeMaxDynamicSharedMemorySize, SMEM_MM);
    cudaFuncSetAttribute(k_hmm, cudaFuncAttributeMaxDynamicSharedMemorySize, SMEM_HMM);
    cudaFuncSetAttribute(k_tf_ln, cudaFuncAttributeMaxDynamicSharedMemorySize, SMEM_TF);
    k_w<<<64, 256>>>(Wt);
    k_wp<<<64, 256>>>(Wp);
    k_hmm<<<NN / BM, 256, SMEM_HMM>>>(x, bt);
    k_adj_mm<<<(NN / BM) * KSPLIT, 256, SMEM_MM>>>(adj);
    k_tf_ln<<<NN / BM2, 256, SMEM_TF>>>(x, bp, gamma, beta, out);
}